// round 15
// baseline (speedup 1.0000x reference)
#include <cuda_runtime.h>
#include <cuda_fp16.h>
#include <cstdint>
#include <math.h>

// Problem constants
#define NROWS 8192
#define DIM   512
#define NCLS  64
#define NB    64          // 8192/128 block-cols
#define NTRI  2080        // 64*65/2 triangular tiles
#define NSLICE 64
#define INV_T 14.285714285714286f
#define FXSCALE 268435456.0f          // 2^28 fixed-point scale

// ---------------- scratch ----------------
__device__ alignas(128) __half g_fh16[NROWS * DIM];          // 8 MB f16 normalized
__device__ float g_Epart[NROWS][NB];                         // 2 MB exp partial sums
__device__ float g_Spart[NSLICE][NCLS * DIM];                // 8 MB class partials
__device__ float g_S[NCLS * DIM];
__device__ float g_Pc[NROWS];                                // per-row precomputed (P - c/T)/cm
__device__ float g_Cf[NROWS];                                // per-row cf/cm (0 if invalid)
__device__ int   g_cnt[NCLS];
__device__ int   g_glab[NROWS];
__device__ unsigned long long g_acc;                         // fixed-point loss accumulator
__device__ int   g_vcnt;                                     // valid-row count
__device__ int   g_done;                                     // last-block ticket

// ---------------- helpers ----------------
__device__ __forceinline__ uint32_t smem_u32(const void* p) {
    uint32_t a;
    asm("{ .reg .u64 t; cvta.to.shared.u64 t, %1; cvt.u32.u64 %0, t; }" : "=r"(a) : "l"(p));
    return a;
}
__device__ __forceinline__ void cp16(uint32_t dst, const void* src) {
    asm volatile("cp.async.cg.shared.global [%0], [%1], 16;" :: "r"(dst), "l"(src) : "memory");
}
#define CP_COMMIT() asm volatile("cp.async.commit_group;" ::: "memory")
#define CP_WAIT(n)  asm volatile("cp.async.wait_group %0;" :: "n"(n) : "memory")

__device__ __forceinline__ void ldsm_x4(uint32_t& r0, uint32_t& r1, uint32_t& r2, uint32_t& r3,
                                        uint32_t addr) {
    asm volatile("ldmatrix.sync.aligned.m8n8.x4.shared.b16 {%0,%1,%2,%3}, [%4];"
                 : "=r"(r0), "=r"(r1), "=r"(r2), "=r"(r3) : "r"(addr));
}
__device__ __forceinline__ void ldsm_x2(uint32_t& r0, uint32_t& r1, uint32_t addr) {
    asm volatile("ldmatrix.sync.aligned.m8n8.x2.shared.b16 {%0,%1}, [%2];"
                 : "=r"(r0), "=r"(r1) : "r"(addr));
}
__device__ __forceinline__ void mma16816(float* c, const uint32_t* a, const uint32_t* b) {
    asm volatile("mma.sync.aligned.m16n8k16.row.col.f32.f16.f16.f32 "
                 "{%0,%1,%2,%3}, {%4,%5,%6,%7}, {%8,%9}, {%0,%1,%2,%3};"
                 : "+f"(c[0]), "+f"(c[1]), "+f"(c[2]), "+f"(c[3])
                 : "r"(a[0]), "r"(a[1]), "r"(a[2]), "r"(a[3]), "r"(b[0]), "r"(b[1]));
}

// ---------------- 1. normalize -> f16 + labels + counter resets ----------------
__global__ void norm_kernel(const float* __restrict__ feat,
                            const int* __restrict__ labels,
                            const int* __restrict__ kptr) {
    int row = blockIdx.x;
    if (row == 0 && threadIdx.x == 0) { g_acc = 0ull; g_vcnt = 0; g_done = 0; }
    const float4* fr4 = (const float4*)(feat + (size_t)row * DIM);
    float4 v = fr4[threadIdx.x];                 // 128 threads x 4 = 512
    float s = v.x * v.x + v.y * v.y + v.z * v.z + v.w * v.w;
    __shared__ float sh[4];
    #pragma unroll
    for (int o = 16; o; o >>= 1) s += __shfl_xor_sync(0xffffffffu, s, o);
    if ((threadIdx.x & 31) == 0) sh[threadIdx.x >> 5] = s;
    __syncthreads();
    float tot = sh[0] + sh[1] + sh[2] + sh[3];
    float inv = 1.0f / fmaxf(sqrtf(tot), 1e-12f);
    __half2 h0 = __floats2half2_rn(v.x * inv, v.y * inv);
    __half2 h1 = __floats2half2_rn(v.z * inv, v.w * inv);
    uint2 packed = make_uint2(*(uint32_t*)&h0, *(uint32_t*)&h1);
    ((uint2*)(g_fh16 + (size_t)row * DIM))[threadIdx.x] = packed;
    if (threadIdx.x == 0) {
        int k = kptr[0];
        g_glab[row] = labels[(row / k) * k];
    }
}

// ---------------- 2a. class partial sums over row slices ----------------
__global__ void classpart_kernel() {
    extern __shared__ float accsh[];       // [NCLS * DIM] = 128 KB
    int slice = blockIdx.x, tid = threadIdx.x;
    for (int i = tid; i < NCLS * DIM; i += blockDim.x) accsh[i] = 0.f;
    __syncthreads();
    for (int r = 0; r < NROWS / NSLICE; r++) {
        int row = slice * (NROWS / NSLICE) + r;
        int lab = g_glab[row];
        accsh[lab * DIM + tid] += __half2float(g_fh16[(size_t)row * DIM + tid]);
    }
    __syncthreads();
    for (int i = tid; i < NCLS * DIM; i += blockDim.x) g_Spart[slice][i] = accsh[i];
}

// ---------------- 2b. reduce partials + class counts ----------------
__global__ void classred_kernel() {
    int c = blockIdx.x, d = threadIdx.x;   // 64 blocks x 512
    float s = 0.f;
    for (int sl = 0; sl < NSLICE; sl++) s += g_Spart[sl][c * DIM + d];
    g_S[c * DIM + d] = s;
    int cnt = 0;
    for (int i = d; i < NROWS; i += 512) cnt += (g_glab[i] == c);
    #pragma unroll
    for (int o = 16; o; o >>= 1) cnt += __shfl_xor_sync(0xffffffffu, cnt, o);
    __shared__ int csh[16];
    if ((d & 31) == 0) csh[d >> 5] = cnt;
    __syncthreads();
    if (d == 0) {
        int tot = 0;
        for (int w = 0; w < 16; w++) tot += csh[w];
        g_cnt[c] = tot;
    }
}

// ---------------- 2c. per-row loss constants (hidden behind simexp) ----------------
__global__ void dotp_kernel() {
    int warp = threadIdx.x >> 5, lane = threadIdx.x & 31;
    int row = blockIdx.x * 8 + warp;
    int gl = g_glab[row];
    const __half2* f2 = (const __half2*)(g_fh16 + (size_t)row * DIM);
    const float2* s2 = (const float2*)(g_S + gl * DIM);
    float dss = 0.f;
    #pragma unroll
    for (int d = lane; d < DIM / 2; d += 32) {
        float2 fv = __half22float2(f2[d]);
        float2 sv = s2[d];
        dss += fv.x * sv.x + fv.y * sv.y;
    }
    #pragma unroll
    for (int o = 16; o; o >>= 1) dss += __shfl_xor_sync(0xffffffffu, dss, o);
    if (lane == 0) {
        int c = g_cnt[gl] - 1;
        float P = (dss - 1.0f) * INV_T;       // f.f == 1 analytically
        float cf = (float)c;
        float cm = fmaxf(cf, 1.0f);
        g_Pc[row] = (c > 0) ? (P - cf * INV_T) / cm : 0.0f;
        g_Cf[row] = (c > 0) ? cf / cm : 0.0f;
    }
}

// ---------------- 3. f16 HMMA triangular GEMM + exp row/col sums ----------------
#define ROWPADB 80
#define STAGEB  (128 * ROWPADB)     // 10240 B per operand per stage
#define NSTAGE  4
#define NKIT    16                  // 512 / 32
#define SMEM_GEMM (2 * NSTAGE * STAGEB)   // 81920 B

__global__ __launch_bounds__(256, 2) void simexp_mma() {
    extern __shared__ char dsm[];
    __shared__ float rbuf[128][4];
    __shared__ float cbuf[128][2];

    int t = blockIdx.x, by = 0;
    while (t >= NB - by) { t -= NB - by; by++; }
    int bx = by + t;
    bool diag = (bx == by);

    int tid = threadIdx.x, lane = tid & 31, wid = tid >> 5;
    int wm = wid >> 2, wn = wid & 3;            // 2x4 warp grid

    uint32_t sA = smem_u32(dsm);
    uint32_t sB = sA + NSTAGE * STAGEB;

    // loader: 4 threads per row (16B each), rows lr and lr+64; row = 1024 B in gmem
    int lr  = tid >> 2;
    int lco = (tid & 3) * 16;
    const char* Ag = (const char*)(g_fh16 + (size_t)(by * 128) * DIM);
    const char* Bg = (const char*)(g_fh16 + (size_t)(bx * 128) * DIM);

    #define LOADC(st, k) do {                                                         \
        int kbyte = (k) * 64;                                                         \
        _Pragma("unroll")                                                             \
        for (int h = 0; h < 2; h++) {                                                 \
            int r = lr + 64 * h;                                                      \
            cp16(sA + (st) * STAGEB + r * ROWPADB + lco, Ag + (size_t)r * 1024 + kbyte + lco); \
            cp16(sB + (st) * STAGEB + r * ROWPADB + lco, Bg + (size_t)r * 1024 + kbyte + lco); \
        }                                                                              \
        CP_COMMIT();                                                                   \
    } while (0)

    float acc[4][4][4];
    #pragma unroll
    for (int i = 0; i < 4; i++)
        #pragma unroll
        for (int j = 0; j < 4; j++)
            #pragma unroll
            for (int v = 0; v < 4; v++) acc[i][j][v] = 0.f;

    LOADC(0, 0);
    LOADC(1, 1);
    LOADC(2, 2);

    for (int k = 0; k < NKIT; k++) {
        if (k < NKIT - 2)       CP_WAIT(2);
        else if (k == NKIT - 2) CP_WAIT(1);
        else                    CP_WAIT(0);
        __syncthreads();   // stage k&3 ready; all warps done consuming stage (k-1)&3
        int st = k & 3;
        uint32_t aBase = sA + st * STAGEB;
        uint32_t bBase = sB + st * STAGEB;
        #pragma unroll
        for (int ks = 0; ks < 2; ks++) {
            uint32_t a[4][4], b[4][2];
            #pragma unroll
            for (int mt = 0; mt < 4; mt++) {
                uint32_t addr = aBase + (uint32_t)(wm * 64 + mt * 16 + (lane & 15)) * ROWPADB
                              + ks * 32 + ((lane >> 4) & 1) * 16;
                ldsm_x4(a[mt][0], a[mt][1], a[mt][2], a[mt][3], addr);
            }
            #pragma unroll
            for (int nt = 0; nt < 4; nt++) {
                uint32_t addr = bBase + (uint32_t)(wn * 32 + nt * 8 + (lane & 7)) * ROWPADB
                              + ks * 32 + ((lane >> 3) & 1) * 16;
                ldsm_x2(b[nt][0], b[nt][1], addr);
            }
            #pragma unroll
            for (int mt = 0; mt < 4; mt++)
                #pragma unroll
                for (int nt = 0; nt < 4; nt++)
                    mma16816(acc[mt][nt], a[mt], b[nt]);
        }
        if (k + 3 < NKIT) LOADC((k + 3) & 3, k + 3);
    }

    // ---- epilogue: e = exp((c-1)/T), row + col partial sums ----
    float rs[4][2], cs[4][2];
    #pragma unroll
    for (int i = 0; i < 4; i++) { rs[i][0] = rs[i][1] = 0.f; cs[i][0] = cs[i][1] = 0.f; }

    int RM = wm * 64, CN = wn * 32;
    #pragma unroll
    for (int mt = 0; mt < 4; mt++) {
        int r0 = RM + mt * 16 + (lane >> 2);
        int r1 = r0 + 8;
        #pragma unroll
        for (int nt = 0; nt < 4; nt++) {
            int c0 = CN + nt * 8 + ((lane & 3) << 1);
            int c1 = c0 + 1;
            float e0 = __expf((acc[mt][nt][0] - 1.0f) * INV_T);
            float e1 = __expf((acc[mt][nt][1] - 1.0f) * INV_T);
            float e2 = __expf((acc[mt][nt][2] - 1.0f) * INV_T);
            float e3 = __expf((acc[mt][nt][3] - 1.0f) * INV_T);
            if (diag) {
                if (r0 == c0) e0 = 0.f;
                if (r0 == c1) e1 = 0.f;
                if (r1 == c0) e2 = 0.f;
                if (r1 == c1) e3 = 0.f;
            }
            rs[mt][0] += e0 + e1;
            rs[mt][1] += e2 + e3;
            cs[nt][0] += e0 + e2;
            cs[nt][1] += e1 + e3;
        }
    }
    // row sums: reduce over lane bits 0-1
    #pragma unroll
    for (int mt = 0; mt < 4; mt++) {
        #pragma unroll
        for (int h = 0; h < 2; h++) {
            rs[mt][h] += __shfl_xor_sync(0xffffffffu, rs[mt][h], 1);
            rs[mt][h] += __shfl_xor_sync(0xffffffffu, rs[mt][h], 2);
        }
        if ((lane & 3) == 0) {
            rbuf[RM + mt * 16 + (lane >> 2)][wn]     = rs[mt][0];
            rbuf[RM + mt * 16 + (lane >> 2) + 8][wn] = rs[mt][1];
        }
    }
    // col sums: reduce over lane bits 2-4
    #pragma unroll
    for (int nt = 0; nt < 4; nt++) {
        #pragma unroll
        for (int v = 0; v < 2; v++) {
            cs[nt][v] += __shfl_xor_sync(0xffffffffu, cs[nt][v], 4);
            cs[nt][v] += __shfl_xor_sync(0xffffffffu, cs[nt][v], 8);
            cs[nt][v] += __shfl_xor_sync(0xffffffffu, cs[nt][v], 16);
        }
        if (lane < 4) {
            cbuf[CN + nt * 8 + lane * 2][wm]     = cs[nt][0];
            cbuf[CN + nt * 8 + lane * 2 + 1][wm] = cs[nt][1];
        }
    }
    __syncthreads();
    if (tid < 128) {
        g_Epart[by * 128 + tid][bx] = rbuf[tid][0] + rbuf[tid][1] + rbuf[tid][2] + rbuf[tid][3];
    } else if (!diag) {
        int c = tid - 128;
        g_Epart[bx * 128 + c][by] = cbuf[c][0] + cbuf[c][1];
    }
    #undef LOADC
}

// ---------------- 4. final: E-sum + loss, deterministic fixed-point reduce ----------------
// 64 blocks x 256 threads; each warp processes 16 rows. Fewer ticket atomics,
// single dispatch wave.
__global__ void final_kernel(float* __restrict__ out) {
    int warp = threadIdx.x >> 5, lane = threadIdx.x & 31;
    float csum = 0.f;
    int vsum = 0;
    #pragma unroll 4
    for (int r = 0; r < 16; r++) {
        int row = (blockIdx.x * 8 + warp) * 16 + r;
        float2 e2 = ((const float2*)g_Epart[row])[lane];
        float E = e2.x + e2.y;
        #pragma unroll
        for (int o = 16; o; o >>= 1) E += __shfl_xor_sync(0xffffffffu, E, o);
        if (lane == 0) {
            float B = g_Cf[row];
            if (B > 0.f) {
                float denom = E + 1e-8f;
                csum += -(g_Pc[row] - B * logf(denom));
                vsum += 1;
            }
        }
    }
    __shared__ float csm[8];
    __shared__ int   vsm[8];
    if (lane == 0) { csm[warp] = csum; vsm[warp] = vsum; }
    __syncthreads();
    if (threadIdx.x == 0) {
        float ts = 0.f; int tv = 0;
        #pragma unroll
        for (int w = 0; w < 8; w++) { ts += csm[w]; tv += vsm[w]; }
        long long q = (long long)llrintf(ts * FXSCALE);
        atomicAdd(&g_acc, (unsigned long long)q);     // two's-complement add: exact, associative
        atomicAdd(&g_vcnt, tv);
        __threadfence();
        int done = atomicAdd(&g_done, 1);
        if (done == (int)gridDim.x - 1) {
            long long total = (long long)g_acc;
            double s = (double)total * (1.0 / (double)FXSCALE);
            int nv = g_vcnt;
            out[0] = (float)(s / (double)(nv > 0 ? nv : 1));
        }
    }
}

// ---------------- launch (side-stream hides all non-GEMM prep) ----------------
extern "C" void kernel_launch(void* const* d_in, const int* in_sizes, int n_in,
                              void* d_out, int out_size) {
    const float* feat   = (const float*)d_in[0];
    const int*   labels = (const int*)d_in[1];
    const int*   kptr   = (const int*)d_in[2];
    float* out = (float*)d_out;

    static cudaStream_t s_side = nullptr;
    static cudaEvent_t  ev_fork = nullptr, ev_join = nullptr;
    if (s_side == nullptr) {
        cudaStreamCreateWithFlags(&s_side, cudaStreamNonBlocking);
        cudaEventCreateWithFlags(&ev_fork, cudaEventDisableTiming);
        cudaEventCreateWithFlags(&ev_join, cudaEventDisableTiming);
        cudaFuncSetAttribute(classpart_kernel, cudaFuncAttributeMaxDynamicSharedMemorySize,
                             NCLS * DIM * (int)sizeof(float));
        cudaFuncSetAttribute(simexp_mma, cudaFuncAttributeMaxDynamicSharedMemorySize, SMEM_GEMM);
    }

    norm_kernel<<<NROWS, 128>>>(feat, labels, kptr);

    // fork: class sums + positive-dot chain hidden behind simexp
    cudaEventRecord(ev_fork, 0);
    cudaStreamWaitEvent(s_side, ev_fork, 0);
    classpart_kernel<<<NSLICE, 512, NCLS * DIM * sizeof(float), s_side>>>();
    classred_kernel<<<NCLS, DIM, 0, s_side>>>();
    dotp_kernel<<<NROWS / 8, 256, 0, s_side>>>();
    cudaEventRecord(ev_join, s_side);

    simexp_mma<<<NTRI, 256, SMEM_GEMM>>>();

    // join: final needs Epart (main) + Pc/Cf (side)
    cudaStreamWaitEvent(0, ev_join, 0);
    final_kernel<<<NB, 256>>>(out);
}

// round 16
// speedup vs baseline: 1.0482x; 1.0482x over previous
#include <cuda_runtime.h>
#include <cuda_fp16.h>
#include <cstdint>
#include <math.h>

// Problem constants
#define NROWS 8192
#define DIM   512
#define NCLS  64
#define NB    64          // 8192/128 block-cols
#define NTRI  2080        // 64*65/2 triangular tiles
#define NSLICE 64
#define INV_T 14.285714285714286f
#define FXSCALE 268435456.0f          // 2^28 fixed-point scale

// ---------------- scratch ----------------
__device__ alignas(128) __half g_fh16[NROWS * DIM];          // 8 MB f16 normalized
__device__ float g_Epart[NROWS][NB];                         // 2 MB exp partial sums
__device__ float g_Spart[NSLICE][NCLS * DIM];                // 8 MB class partials
__device__ float g_S[NCLS * DIM];
__device__ float g_Pc[NROWS];                                // per-row precomputed (P - c/T)/cm
__device__ float g_Cf[NROWS];                                // per-row cf/cm (0 if invalid)
__device__ int   g_cnt[NCLS];
__device__ int   g_glab[NROWS];
__device__ unsigned long long g_acc;                         // fixed-point loss accumulator
__device__ int   g_vcnt;                                     // valid-row count
__device__ int   g_done;                                     // last-block ticket

// ---------------- helpers ----------------
__device__ __forceinline__ uint32_t smem_u32(const void* p) {
    uint32_t a;
    asm("{ .reg .u64 t; cvta.to.shared.u64 t, %1; cvt.u32.u64 %0, t; }" : "=r"(a) : "l"(p));
    return a;
}
__device__ __forceinline__ void cp16(uint32_t dst, const void* src) {
    asm volatile("cp.async.cg.shared.global [%0], [%1], 16;" :: "r"(dst), "l"(src) : "memory");
}
#define CP_COMMIT() asm volatile("cp.async.commit_group;" ::: "memory")
#define CP_WAIT(n)  asm volatile("cp.async.wait_group %0;" :: "n"(n) : "memory")

__device__ __forceinline__ void ldsm_x4(uint32_t& r0, uint32_t& r1, uint32_t& r2, uint32_t& r3,
                                        uint32_t addr) {
    asm volatile("ldmatrix.sync.aligned.m8n8.x4.shared.b16 {%0,%1,%2,%3}, [%4];"
                 : "=r"(r0), "=r"(r1), "=r"(r2), "=r"(r3) : "r"(addr));
}
__device__ __forceinline__ void ldsm_x2(uint32_t& r0, uint32_t& r1, uint32_t addr) {
    asm volatile("ldmatrix.sync.aligned.m8n8.x2.shared.b16 {%0,%1}, [%2];"
                 : "=r"(r0), "=r"(r1) : "r"(addr));
}
__device__ __forceinline__ void mma16816(float* c, const uint32_t* a, const uint32_t* b) {
    asm volatile("mma.sync.aligned.m16n8k16.row.col.f32.f16.f16.f32 "
                 "{%0,%1,%2,%3}, {%4,%5,%6,%7}, {%8,%9}, {%0,%1,%2,%3};"
                 : "+f"(c[0]), "+f"(c[1]), "+f"(c[2]), "+f"(c[3])
                 : "r"(a[0]), "r"(a[1]), "r"(a[2]), "r"(a[3]), "r"(b[0]), "r"(b[1]));
}

// ---------------- 1. normalize -> f16: one warp per row, shfl-only ----------------
// 1024 blocks x 256 threads; warp w of block b handles row b*8+w.
__global__ void norm_kernel(const float* __restrict__ feat,
                            const int* __restrict__ labels,
                            const int* __restrict__ kptr) {
    int warp = threadIdx.x >> 5, lane = threadIdx.x & 31;
    int row = blockIdx.x * 8 + warp;
    if (row == 0 && lane == 0) { g_acc = 0ull; g_vcnt = 0; g_done = 0; }

    const float4* fr4 = (const float4*)(feat + (size_t)row * DIM);
    float4 v[4];
    float s = 0.f;
    #pragma unroll
    for (int i = 0; i < 4; i++) {
        v[i] = fr4[lane + 32 * i];
        s += v[i].x * v[i].x + v[i].y * v[i].y + v[i].z * v[i].z + v[i].w * v[i].w;
    }
    #pragma unroll
    for (int o = 16; o; o >>= 1) s += __shfl_xor_sync(0xffffffffu, s, o);
    float inv = 1.0f / fmaxf(sqrtf(s), 1e-12f);

    uint2* dst = (uint2*)(g_fh16 + (size_t)row * DIM);
    #pragma unroll
    for (int i = 0; i < 4; i++) {
        __half2 h0 = __floats2half2_rn(v[i].x * inv, v[i].y * inv);
        __half2 h1 = __floats2half2_rn(v[i].z * inv, v[i].w * inv);
        dst[lane + 32 * i] = make_uint2(*(uint32_t*)&h0, *(uint32_t*)&h1);
    }
    if (lane == 0) {
        int k = kptr[0];
        g_glab[row] = labels[(row / k) * k];
    }
}

// ---------------- 2a. class partial sums over row slices ----------------
__global__ void classpart_kernel() {
    extern __shared__ float accsh[];       // [NCLS * DIM] = 128 KB
    int slice = blockIdx.x, tid = threadIdx.x;
    for (int i = tid; i < NCLS * DIM; i += blockDim.x) accsh[i] = 0.f;
    __syncthreads();
    for (int r = 0; r < NROWS / NSLICE; r++) {
        int row = slice * (NROWS / NSLICE) + r;
        int lab = g_glab[row];
        accsh[lab * DIM + tid] += __half2float(g_fh16[(size_t)row * DIM + tid]);
    }
    __syncthreads();
    for (int i = tid; i < NCLS * DIM; i += blockDim.x) g_Spart[slice][i] = accsh[i];
}

// ---------------- 2b. reduce partials + class counts ----------------
__global__ void classred_kernel() {
    int c = blockIdx.x, d = threadIdx.x;   // 64 blocks x 512
    float s = 0.f;
    for (int sl = 0; sl < NSLICE; sl++) s += g_Spart[sl][c * DIM + d];
    g_S[c * DIM + d] = s;
    int cnt = 0;
    for (int i = d; i < NROWS; i += 512) cnt += (g_glab[i] == c);
    #pragma unroll
    for (int o = 16; o; o >>= 1) cnt += __shfl_xor_sync(0xffffffffu, cnt, o);
    __shared__ int csh[16];
    if ((d & 31) == 0) csh[d >> 5] = cnt;
    __syncthreads();
    if (d == 0) {
        int tot = 0;
        for (int w = 0; w < 16; w++) tot += csh[w];
        g_cnt[c] = tot;
    }
}

// ---------------- 2c. per-row loss constants (hidden behind simexp) ----------------
__global__ void dotp_kernel() {
    int warp = threadIdx.x >> 5, lane = threadIdx.x & 31;
    int row = blockIdx.x * 8 + warp;
    int gl = g_glab[row];
    const __half2* f2 = (const __half2*)(g_fh16 + (size_t)row * DIM);
    const float2* s2 = (const float2*)(g_S + gl * DIM);
    float dss = 0.f;
    #pragma unroll
    for (int d = lane; d < DIM / 2; d += 32) {
        float2 fv = __half22float2(f2[d]);
        float2 sv = s2[d];
        dss += fv.x * sv.x + fv.y * sv.y;
    }
    #pragma unroll
    for (int o = 16; o; o >>= 1) dss += __shfl_xor_sync(0xffffffffu, dss, o);
    if (lane == 0) {
        int c = g_cnt[gl] - 1;
        float P = (dss - 1.0f) * INV_T;       // f.f == 1 analytically
        float cf = (float)c;
        float cm = fmaxf(cf, 1.0f);
        g_Pc[row] = (c > 0) ? (P - cf * INV_T) / cm : 0.0f;
        g_Cf[row] = (c > 0) ? cf / cm : 0.0f;
    }
}

// ---------------- 3. f16 HMMA triangular GEMM + exp row/col sums ----------------
#define ROWPADB 80
#define STAGEB  (128 * ROWPADB)     // 10240 B per operand per stage
#define NSTAGE  4
#define NKIT    16                  // 512 / 32
#define SMEM_GEMM (2 * NSTAGE * STAGEB)   // 81920 B

__global__ __launch_bounds__(256, 2) void simexp_mma() {
    extern __shared__ char dsm[];
    __shared__ float rbuf[128][4];
    __shared__ float cbuf[128][2];

    int t = blockIdx.x, by = 0;
    while (t >= NB - by) { t -= NB - by; by++; }
    int bx = by + t;
    bool diag = (bx == by);

    int tid = threadIdx.x, lane = tid & 31, wid = tid >> 5;
    int wm = wid >> 2, wn = wid & 3;            // 2x4 warp grid

    uint32_t sA = smem_u32(dsm);
    uint32_t sB = sA + NSTAGE * STAGEB;

    // loader: 4 threads per row (16B each), rows lr and lr+64; row = 1024 B in gmem
    int lr  = tid >> 2;
    int lco = (tid & 3) * 16;
    const char* Ag = (const char*)(g_fh16 + (size_t)(by * 128) * DIM);
    const char* Bg = (const char*)(g_fh16 + (size_t)(bx * 128) * DIM);

    #define LOADC(st, k) do {                                                         \
        int kbyte = (k) * 64;                                                         \
        _Pragma("unroll")                                                             \
        for (int h = 0; h < 2; h++) {                                                 \
            int r = lr + 64 * h;                                                      \
            cp16(sA + (st) * STAGEB + r * ROWPADB + lco, Ag + (size_t)r * 1024 + kbyte + lco); \
            cp16(sB + (st) * STAGEB + r * ROWPADB + lco, Bg + (size_t)r * 1024 + kbyte + lco); \
        }                                                                              \
        CP_COMMIT();                                                                   \
    } while (0)

    float acc[4][4][4];
    #pragma unroll
    for (int i = 0; i < 4; i++)
        #pragma unroll
        for (int j = 0; j < 4; j++)
            #pragma unroll
            for (int v = 0; v < 4; v++) acc[i][j][v] = 0.f;

    LOADC(0, 0);
    LOADC(1, 1);
    LOADC(2, 2);

    for (int k = 0; k < NKIT; k++) {
        if (k < NKIT - 2)       CP_WAIT(2);
        else if (k == NKIT - 2) CP_WAIT(1);
        else                    CP_WAIT(0);
        __syncthreads();   // stage k&3 ready; all warps done consuming stage (k-1)&3
        int st = k & 3;
        uint32_t aBase = sA + st * STAGEB;
        uint32_t bBase = sB + st * STAGEB;
        #pragma unroll
        for (int ks = 0; ks < 2; ks++) {
            uint32_t a[4][4], b[4][2];
            #pragma unroll
            for (int mt = 0; mt < 4; mt++) {
                uint32_t addr = aBase + (uint32_t)(wm * 64 + mt * 16 + (lane & 15)) * ROWPADB
                              + ks * 32 + ((lane >> 4) & 1) * 16;
                ldsm_x4(a[mt][0], a[mt][1], a[mt][2], a[mt][3], addr);
            }
            #pragma unroll
            for (int nt = 0; nt < 4; nt++) {
                uint32_t addr = bBase + (uint32_t)(wn * 32 + nt * 8 + (lane & 7)) * ROWPADB
                              + ks * 32 + ((lane >> 3) & 1) * 16;
                ldsm_x2(b[nt][0], b[nt][1], addr);
            }
            #pragma unroll
            for (int mt = 0; mt < 4; mt++)
                #pragma unroll
                for (int nt = 0; nt < 4; nt++)
                    mma16816(acc[mt][nt], a[mt], b[nt]);
        }
        if (k + 3 < NKIT) LOADC((k + 3) & 3, k + 3);
    }

    // ---- epilogue: e = exp((c-1)/T), row + col partial sums ----
    float rs[4][2], cs[4][2];
    #pragma unroll
    for (int i = 0; i < 4; i++) { rs[i][0] = rs[i][1] = 0.f; cs[i][0] = cs[i][1] = 0.f; }

    int RM = wm * 64, CN = wn * 32;
    #pragma unroll
    for (int mt = 0; mt < 4; mt++) {
        int r0 = RM + mt * 16 + (lane >> 2);
        int r1 = r0 + 8;
        #pragma unroll
        for (int nt = 0; nt < 4; nt++) {
            int c0 = CN + nt * 8 + ((lane & 3) << 1);
            int c1 = c0 + 1;
            float e0 = __expf((acc[mt][nt][0] - 1.0f) * INV_T);
            float e1 = __expf((acc[mt][nt][1] - 1.0f) * INV_T);
            float e2 = __expf((acc[mt][nt][2] - 1.0f) * INV_T);
            float e3 = __expf((acc[mt][nt][3] - 1.0f) * INV_T);
            if (diag) {
                if (r0 == c0) e0 = 0.f;
                if (r0 == c1) e1 = 0.f;
                if (r1 == c0) e2 = 0.f;
                if (r1 == c1) e3 = 0.f;
            }
            rs[mt][0] += e0 + e1;
            rs[mt][1] += e2 + e3;
            cs[nt][0] += e0 + e2;
            cs[nt][1] += e1 + e3;
        }
    }
    // row sums: reduce over lane bits 0-1
    #pragma unroll
    for (int mt = 0; mt < 4; mt++) {
        #pragma unroll
        for (int h = 0; h < 2; h++) {
            rs[mt][h] += __shfl_xor_sync(0xffffffffu, rs[mt][h], 1);
            rs[mt][h] += __shfl_xor_sync(0xffffffffu, rs[mt][h], 2);
        }
        if ((lane & 3) == 0) {
            rbuf[RM + mt * 16 + (lane >> 2)][wn]     = rs[mt][0];
            rbuf[RM + mt * 16 + (lane >> 2) + 8][wn] = rs[mt][1];
        }
    }
    // col sums: reduce over lane bits 2-4
    #pragma unroll
    for (int nt = 0; nt < 4; nt++) {
        #pragma unroll
        for (int v = 0; v < 2; v++) {
            cs[nt][v] += __shfl_xor_sync(0xffffffffu, cs[nt][v], 4);
            cs[nt][v] += __shfl_xor_sync(0xffffffffu, cs[nt][v], 8);
            cs[nt][v] += __shfl_xor_sync(0xffffffffu, cs[nt][v], 16);
        }
        if (lane < 4) {
            cbuf[CN + nt * 8 + lane * 2][wm]     = cs[nt][0];
            cbuf[CN + nt * 8 + lane * 2 + 1][wm] = cs[nt][1];
        }
    }
    __syncthreads();
    if (tid < 128) {
        g_Epart[by * 128 + tid][bx] = rbuf[tid][0] + rbuf[tid][1] + rbuf[tid][2] + rbuf[tid][3];
    } else if (!diag) {
        int c = tid - 128;
        g_Epart[bx * 128 + c][by] = cbuf[c][0] + cbuf[c][1];
    }
    #undef LOADC
}

// ---------------- 4. final: E-sum + loss, deterministic fixed-point reduce ----------------
// 256 blocks x 256 threads; each warp processes 4 rows (R14 shape — measured best).
__global__ void final_kernel(float* __restrict__ out) {
    int warp = threadIdx.x >> 5, lane = threadIdx.x & 31;
    float csum = 0.f;
    int vsum = 0;
    #pragma unroll
    for (int r = 0; r < 4; r++) {
        int row = (blockIdx.x * 8 + warp) * 4 + r;
        float2 e2 = ((const float2*)g_Epart[row])[lane];
        float E = e2.x + e2.y;
        #pragma unroll
        for (int o = 16; o; o >>= 1) E += __shfl_xor_sync(0xffffffffu, E, o);
        if (lane == 0) {
            float B = g_Cf[row];
            if (B > 0.f) {
                float denom = E + 1e-8f;
                csum += -(g_Pc[row] - B * logf(denom));
                vsum += 1;
            }
        }
    }
    __shared__ float csm[8];
    __shared__ int   vsm[8];
    if (lane == 0) { csm[warp] = csum; vsm[warp] = vsum; }
    __syncthreads();
    if (threadIdx.x == 0) {
        float ts = 0.f; int tv = 0;
        #pragma unroll
        for (int w = 0; w < 8; w++) { ts += csm[w]; tv += vsm[w]; }
        long long q = (long long)llrintf(ts * FXSCALE);
        atomicAdd(&g_acc, (unsigned long long)q);     // two's-complement add: exact, associative
        atomicAdd(&g_vcnt, tv);
        __threadfence();
        int done = atomicAdd(&g_done, 1);
        if (done == (int)gridDim.x - 1) {
            long long total = (long long)g_acc;
            double s = (double)total * (1.0 / (double)FXSCALE);
            int nv = g_vcnt;
            out[0] = (float)(s / (double)(nv > 0 ? nv : 1));
        }
    }
}

// ---------------- launch (side-stream hides all non-GEMM prep) ----------------
extern "C" void kernel_launch(void* const* d_in, const int* in_sizes, int n_in,
                              void* d_out, int out_size) {
    const float* feat   = (const float*)d_in[0];
    const int*   labels = (const int*)d_in[1];
    const int*   kptr   = (const int*)d_in[2];
    float* out = (float*)d_out;

    static cudaStream_t s_side = nullptr;
    static cudaEvent_t  ev_fork = nullptr, ev_join = nullptr;
    if (s_side == nullptr) {
        cudaStreamCreateWithFlags(&s_side, cudaStreamNonBlocking);
        cudaEventCreateWithFlags(&ev_fork, cudaEventDisableTiming);
        cudaEventCreateWithFlags(&ev_join, cudaEventDisableTiming);
        cudaFuncSetAttribute(classpart_kernel, cudaFuncAttributeMaxDynamicSharedMemorySize,
                             NCLS * DIM * (int)sizeof(float));
        cudaFuncSetAttribute(simexp_mma, cudaFuncAttributeMaxDynamicSharedMemorySize, SMEM_GEMM);
    }

    norm_kernel<<<NROWS / 8, 256>>>(feat, labels, kptr);

    // fork: class sums + positive-dot chain hidden behind simexp
    cudaEventRecord(ev_fork, 0);
    cudaStreamWaitEvent(s_side, ev_fork, 0);
    classpart_kernel<<<NSLICE, 512, NCLS * DIM * sizeof(float), s_side>>>();
    classred_kernel<<<NCLS, DIM, 0, s_side>>>();
    dotp_kernel<<<NROWS / 8, 256, 0, s_side>>>();
    cudaEventRecord(ev_join, s_side);

    simexp_mma<<<NTRI, 256, SMEM_GEMM>>>();

    // join: final needs Epart (main) + Pc/Cf (side)
    cudaStreamWaitEvent(0, ev_join, 0);
    final_kernel<<<NROWS / 32, 256>>>(out);
}

// round 17
// speedup vs baseline: 1.0678x; 1.0186x over previous
#include <cuda_runtime.h>
#include <cuda_fp16.h>
#include <cstdint>
#include <math.h>

// Problem constants
#define NROWS 8192
#define DIM   512
#define NCLS  64
#define NB    64          // 8192/128 block-cols
#define NTRI  2080        // 64*65/2 triangular tiles
#define NSLICE 64
#define INV_T 14.285714285714286f
#define K2    20.617278244602417f    // INV_T * log2(e)
#define FXSCALE 268435456.0f          // 2^28 fixed-point scale

// ---------------- scratch ----------------
__device__ alignas(128) __half g_fh16[NROWS * DIM];          // 8 MB f16 normalized
__device__ float g_Epart[NROWS][NB];                         // 2 MB exp partial sums
__device__ float g_Spart[NSLICE][NCLS * DIM];                // 8 MB class partials
__device__ float g_S[NCLS * DIM];
__device__ float g_Pc[NROWS];                                // per-row precomputed (P - c/T)/cm
__device__ float g_Cf[NROWS];                                // per-row cf/cm (0 if invalid)
__device__ int   g_cnt[NCLS];
__device__ int   g_glab[NROWS];
__device__ unsigned long long g_acc;                         // fixed-point loss accumulator
__device__ int   g_vcnt;                                     // valid-row count
__device__ int   g_done;                                     // last-block ticket

// ---------------- helpers ----------------
__device__ __forceinline__ uint32_t smem_u32(const void* p) {
    uint32_t a;
    asm("{ .reg .u64 t; cvta.to.shared.u64 t, %1; cvt.u32.u64 %0, t; }" : "=r"(a) : "l"(p));
    return a;
}
__device__ __forceinline__ void cp16(uint32_t dst, const void* src) {
    asm volatile("cp.async.cg.shared.global [%0], [%1], 16;" :: "r"(dst), "l"(src) : "memory");
}
#define CP_COMMIT() asm volatile("cp.async.commit_group;" ::: "memory")
#define CP_WAIT(n)  asm volatile("cp.async.wait_group %0;" :: "n"(n) : "memory")

__device__ __forceinline__ void ldsm_x4(uint32_t& r0, uint32_t& r1, uint32_t& r2, uint32_t& r3,
                                        uint32_t addr) {
    asm volatile("ldmatrix.sync.aligned.m8n8.x4.shared.b16 {%0,%1,%2,%3}, [%4];"
                 : "=r"(r0), "=r"(r1), "=r"(r2), "=r"(r3) : "r"(addr));
}
__device__ __forceinline__ void ldsm_x2(uint32_t& r0, uint32_t& r1, uint32_t addr) {
    asm volatile("ldmatrix.sync.aligned.m8n8.x2.shared.b16 {%0,%1}, [%2];"
                 : "=r"(r0), "=r"(r1) : "r"(addr));
}
__device__ __forceinline__ void mma16816(float* c, const uint32_t* a, const uint32_t* b) {
    asm volatile("mma.sync.aligned.m16n8k16.row.col.f32.f16.f16.f32 "
                 "{%0,%1,%2,%3}, {%4,%5,%6,%7}, {%8,%9}, {%0,%1,%2,%3};"
                 : "+f"(c[0]), "+f"(c[1]), "+f"(c[2]), "+f"(c[3])
                 : "r"(a[0]), "r"(a[1]), "r"(a[2]), "r"(a[3]), "r"(b[0]), "r"(b[1]));
}

// ---------------- 1. normalize -> f16: one warp per row, shfl-only ----------------
// 1024 blocks x 256 threads; warp w of block b handles row b*8+w.
__global__ void norm_kernel(const float* __restrict__ feat,
                            const int* __restrict__ labels,
                            const int* __restrict__ kptr) {
    int warp = threadIdx.x >> 5, lane = threadIdx.x & 31;
    int row = blockIdx.x * 8 + warp;
    if (row == 0 && lane == 0) { g_acc = 0ull; g_vcnt = 0; g_done = 0; }

    const float4* fr4 = (const float4*)(feat + (size_t)row * DIM);
    float4 v[4];
    float s = 0.f;
    #pragma unroll
    for (int i = 0; i < 4; i++) {
        v[i] = fr4[lane + 32 * i];
        s += v[i].x * v[i].x + v[i].y * v[i].y + v[i].z * v[i].z + v[i].w * v[i].w;
    }
    #pragma unroll
    for (int o = 16; o; o >>= 1) s += __shfl_xor_sync(0xffffffffu, s, o);
    float inv = 1.0f / fmaxf(sqrtf(s), 1e-12f);

    uint2* dst = (uint2*)(g_fh16 + (size_t)row * DIM);
    #pragma unroll
    for (int i = 0; i < 4; i++) {
        __half2 h0 = __floats2half2_rn(v[i].x * inv, v[i].y * inv);
        __half2 h1 = __floats2half2_rn(v[i].z * inv, v[i].w * inv);
        dst[lane + 32 * i] = make_uint2(*(uint32_t*)&h0, *(uint32_t*)&h1);
    }
    if (lane == 0) {
        int k = kptr[0];
        g_glab[row] = labels[(row / k) * k];
    }
}

// ---------------- 2a. class partial sums over row slices ----------------
__global__ void classpart_kernel() {
    extern __shared__ float accsh[];       // [NCLS * DIM] = 128 KB
    int slice = blockIdx.x, tid = threadIdx.x;
    for (int i = tid; i < NCLS * DIM; i += blockDim.x) accsh[i] = 0.f;
    __syncthreads();
    for (int r = 0; r < NROWS / NSLICE; r++) {
        int row = slice * (NROWS / NSLICE) + r;
        int lab = g_glab[row];
        accsh[lab * DIM + tid] += __half2float(g_fh16[(size_t)row * DIM + tid]);
    }
    __syncthreads();
    for (int i = tid; i < NCLS * DIM; i += blockDim.x) g_Spart[slice][i] = accsh[i];
}

// ---------------- 2b. reduce partials + class counts ----------------
__global__ void classred_kernel() {
    int c = blockIdx.x, d = threadIdx.x;   // 64 blocks x 512
    float s = 0.f;
    for (int sl = 0; sl < NSLICE; sl++) s += g_Spart[sl][c * DIM + d];
    g_S[c * DIM + d] = s;
    int cnt = 0;
    for (int i = d; i < NROWS; i += 512) cnt += (g_glab[i] == c);
    #pragma unroll
    for (int o = 16; o; o >>= 1) cnt += __shfl_xor_sync(0xffffffffu, cnt, o);
    __shared__ int csh[16];
    if ((d & 31) == 0) csh[d >> 5] = cnt;
    __syncthreads();
    if (d == 0) {
        int tot = 0;
        for (int w = 0; w < 16; w++) tot += csh[w];
        g_cnt[c] = tot;
    }
}

// ---------------- 2c. per-row loss constants (hidden behind simexp) ----------------
__global__ void dotp_kernel() {
    int warp = threadIdx.x >> 5, lane = threadIdx.x & 31;
    int row = blockIdx.x * 8 + warp;
    int gl = g_glab[row];
    const __half2* f2 = (const __half2*)(g_fh16 + (size_t)row * DIM);
    const float2* s2 = (const float2*)(g_S + gl * DIM);
    float dss = 0.f;
    #pragma unroll
    for (int d = lane; d < DIM / 2; d += 32) {
        float2 fv = __half22float2(f2[d]);
        float2 sv = s2[d];
        dss += fv.x * sv.x + fv.y * sv.y;
    }
    #pragma unroll
    for (int o = 16; o; o >>= 1) dss += __shfl_xor_sync(0xffffffffu, dss, o);
    if (lane == 0) {
        int c = g_cnt[gl] - 1;
        float P = (dss - 1.0f) * INV_T;       // f.f == 1 analytically
        float cf = (float)c;
        float cm = fmaxf(cf, 1.0f);
        g_Pc[row] = (c > 0) ? (P - cf * INV_T) / cm : 0.0f;
        g_Cf[row] = (c > 0) ? cf / cm : 0.0f;
    }
}

// ---------------- 3. f16 HMMA triangular GEMM + exp row/col sums ----------------
#define ROWPADB 80
#define STAGEB  (128 * ROWPADB)     // 10240 B per operand per stage
#define NSTAGE  4
#define NKIT    16                  // 512 / 32
#define SMEM_GEMM (2 * NSTAGE * STAGEB)   // 81920 B

__global__ __launch_bounds__(256, 2) void simexp_mma() {
    extern __shared__ char dsm[];
    __shared__ float rbuf[128][4];
    __shared__ float cbuf[128][2];

    int t = blockIdx.x, by = 0;
    while (t >= NB - by) { t -= NB - by; by++; }
    int bx = by + t;
    bool diag = (bx == by);

    int tid = threadIdx.x, lane = tid & 31, wid = tid >> 5;
    int wm = wid >> 2, wn = wid & 3;            // 2x4 warp grid

    uint32_t sA = smem_u32(dsm);
    uint32_t sB = sA + NSTAGE * STAGEB;

    // loader: 4 threads per row (16B each), rows lr and lr+64; row = 1024 B in gmem
    int lr  = tid >> 2;
    int lco = (tid & 3) * 16;
    const char* Ag = (const char*)(g_fh16 + (size_t)(by * 128) * DIM);
    const char* Bg = (const char*)(g_fh16 + (size_t)(bx * 128) * DIM);

    #define LOADC(st, k) do {                                                         \
        int kbyte = (k) * 64;                                                         \
        _Pragma("unroll")                                                             \
        for (int h = 0; h < 2; h++) {                                                 \
            int r = lr + 64 * h;                                                      \
            cp16(sA + (st) * STAGEB + r * ROWPADB + lco, Ag + (size_t)r * 1024 + kbyte + lco); \
            cp16(sB + (st) * STAGEB + r * ROWPADB + lco, Bg + (size_t)r * 1024 + kbyte + lco); \
        }                                                                              \
        CP_COMMIT();                                                                   \
    } while (0)

    float acc[4][4][4];
    #pragma unroll
    for (int i = 0; i < 4; i++)
        #pragma unroll
        for (int j = 0; j < 4; j++)
            #pragma unroll
            for (int v = 0; v < 4; v++) acc[i][j][v] = 0.f;

    LOADC(0, 0);
    LOADC(1, 1);
    LOADC(2, 2);

    for (int k = 0; k < NKIT; k++) {
        if (k < NKIT - 2)       CP_WAIT(2);
        else if (k == NKIT - 2) CP_WAIT(1);
        else                    CP_WAIT(0);
        __syncthreads();   // stage k&3 ready; all warps done consuming stage (k-1)&3
        int st = k & 3;
        uint32_t aBase = sA + st * STAGEB;
        uint32_t bBase = sB + st * STAGEB;
        #pragma unroll
        for (int ks = 0; ks < 2; ks++) {
            uint32_t a[4][4], b[4][2];
            #pragma unroll
            for (int mt = 0; mt < 4; mt++) {
                uint32_t addr = aBase + (uint32_t)(wm * 64 + mt * 16 + (lane & 15)) * ROWPADB
                              + ks * 32 + ((lane >> 4) & 1) * 16;
                ldsm_x4(a[mt][0], a[mt][1], a[mt][2], a[mt][3], addr);
            }
            #pragma unroll
            for (int nt = 0; nt < 4; nt++) {
                uint32_t addr = bBase + (uint32_t)(wn * 32 + nt * 8 + (lane & 7)) * ROWPADB
                              + ks * 32 + ((lane >> 3) & 1) * 16;
                ldsm_x2(b[nt][0], b[nt][1], addr);
            }
            #pragma unroll
            for (int mt = 0; mt < 4; mt++)
                #pragma unroll
                for (int nt = 0; nt < 4; nt++)
                    mma16816(acc[mt][nt], a[mt], b[nt]);
        }
        if (k + 3 < NKIT) LOADC((k + 3) & 3, k + 3);
    }

    // ---- epilogue: e = exp2((c-1)*K2) = exp((c-1)/T), row + col partial sums ----
    float rs[4][2], cs[4][2];
    #pragma unroll
    for (int i = 0; i < 4; i++) { rs[i][0] = rs[i][1] = 0.f; cs[i][0] = cs[i][1] = 0.f; }

    int RM = wm * 64, CN = wn * 32;
    #pragma unroll
    for (int mt = 0; mt < 4; mt++) {
        int r0 = RM + mt * 16 + (lane >> 2);
        int r1 = r0 + 8;
        #pragma unroll
        for (int nt = 0; nt < 4; nt++) {
            int c0 = CN + nt * 8 + ((lane & 3) << 1);
            int c1 = c0 + 1;
            float e0 = exp2f(fmaf(acc[mt][nt][0], K2, -K2));
            float e1 = exp2f(fmaf(acc[mt][nt][1], K2, -K2));
            float e2 = exp2f(fmaf(acc[mt][nt][2], K2, -K2));
            float e3 = exp2f(fmaf(acc[mt][nt][3], K2, -K2));
            if (diag) {
                if (r0 == c0) e0 = 0.f;
                if (r0 == c1) e1 = 0.f;
                if (r1 == c0) e2 = 0.f;
                if (r1 == c1) e3 = 0.f;
            }
            rs[mt][0] += e0 + e1;
            rs[mt][1] += e2 + e3;
            cs[nt][0] += e0 + e2;
            cs[nt][1] += e1 + e3;
        }
    }
    // row sums: reduce over lane bits 0-1
    #pragma unroll
    for (int mt = 0; mt < 4; mt++) {
        #pragma unroll
        for (int h = 0; h < 2; h++) {
            rs[mt][h] += __shfl_xor_sync(0xffffffffu, rs[mt][h], 1);
            rs[mt][h] += __shfl_xor_sync(0xffffffffu, rs[mt][h], 2);
        }
        if ((lane & 3) == 0) {
            rbuf[RM + mt * 16 + (lane >> 2)][wn]     = rs[mt][0];
            rbuf[RM + mt * 16 + (lane >> 2) + 8][wn] = rs[mt][1];
        }
    }
    // col sums: reduce over lane bits 2-4
    #pragma unroll
    for (int nt = 0; nt < 4; nt++) {
        #pragma unroll
        for (int v = 0; v < 2; v++) {
            cs[nt][v] += __shfl_xor_sync(0xffffffffu, cs[nt][v], 4);
            cs[nt][v] += __shfl_xor_sync(0xffffffffu, cs[nt][v], 8);
            cs[nt][v] += __shfl_xor_sync(0xffffffffu, cs[nt][v], 16);
        }
        if (lane < 4) {
            cbuf[CN + nt * 8 + lane * 2][wm]     = cs[nt][0];
            cbuf[CN + nt * 8 + lane * 2 + 1][wm] = cs[nt][1];
        }
    }
    __syncthreads();
    if (tid < 128) {
        g_Epart[by * 128 + tid][bx] = rbuf[tid][0] + rbuf[tid][1] + rbuf[tid][2] + rbuf[tid][3];
    } else if (!diag) {
        int c = tid - 128;
        g_Epart[bx * 128 + c][by] = cbuf[c][0] + cbuf[c][1];
    }
    #undef LOADC
}

// ---------------- 4. final: E-sum + loss, deterministic fixed-point reduce ----------------
// 256 blocks x 256 threads; each warp processes 4 rows (R14/R16 shape — measured best).
__global__ void final_kernel(float* __restrict__ out) {
    int warp = threadIdx.x >> 5, lane = threadIdx.x & 31;
    float csum = 0.f;
    int vsum = 0;
    #pragma unroll
    for (int r = 0; r < 4; r++) {
        int row = (blockIdx.x * 8 + warp) * 4 + r;
        float2 e2 = ((const float2*)g_Epart[row])[lane];
        float E = e2.x + e2.y;
        #pragma unroll
        for (int o = 16; o; o >>= 1) E += __shfl_xor_sync(0xffffffffu, E, o);
        if (lane == 0) {
            float B = g_Cf[row];
            if (B > 0.f) {
                float denom = E + 1e-8f;
                csum += -(g_Pc[row] - B * logf(denom));
                vsum += 1;
            }
        }
    }
    __shared__ float csm[8];
    __shared__ int   vsm[8];
    if (lane == 0) { csm[warp] = csum; vsm[warp] = vsum; }
    __syncthreads();
    if (threadIdx.x == 0) {
        float ts = 0.f; int tv = 0;
        #pragma unroll
        for (int w = 0; w < 8; w++) { ts += csm[w]; tv += vsm[w]; }
        long long q = (long long)llrintf(ts * FXSCALE);
        atomicAdd(&g_acc, (unsigned long long)q);     // two's-complement add: exact, associative
        atomicAdd(&g_vcnt, tv);
        __threadfence();
        int done = atomicAdd(&g_done, 1);
        if (done == (int)gridDim.x - 1) {
            long long total = (long long)g_acc;
            double s = (double)total * (1.0 / (double)FXSCALE);
            int nv = g_vcnt;
            out[0] = (float)(s / (double)(nv > 0 ? nv : 1));
        }
    }
}

// ---------------- launch (side-stream hides all non-GEMM prep) ----------------
extern "C" void kernel_launch(void* const* d_in, const int* in_sizes, int n_in,
                              void* d_out, int out_size) {
    const float* feat   = (const float*)d_in[0];
    const int*   labels = (const int*)d_in[1];
    const int*   kptr   = (const int*)d_in[2];
    float* out = (float*)d_out;

    static cudaStream_t s_side = nullptr;
    static cudaEvent_t  ev_fork = nullptr, ev_join = nullptr;
    if (s_side == nullptr) {
        cudaStreamCreateWithFlags(&s_side, cudaStreamNonBlocking);
        cudaEventCreateWithFlags(&ev_fork, cudaEventDisableTiming);
        cudaEventCreateWithFlags(&ev_join, cudaEventDisableTiming);
        cudaFuncSetAttribute(classpart_kernel, cudaFuncAttributeMaxDynamicSharedMemorySize,
                             NCLS * DIM * (int)sizeof(float));
        cudaFuncSetAttribute(simexp_mma, cudaFuncAttributeMaxDynamicSharedMemorySize, SMEM_GEMM);
    }

    norm_kernel<<<NROWS / 8, 256>>>(feat, labels, kptr);

    // fork: class sums + positive-dot chain hidden behind simexp
    cudaEventRecord(ev_fork, 0);
    cudaStreamWaitEvent(s_side, ev_fork, 0);
    classpart_kernel<<<NSLICE, 512, NCLS * DIM * sizeof(float), s_side>>>();
    classred_kernel<<<NCLS, DIM, 0, s_side>>>();
    dotp_kernel<<<NROWS / 8, 256, 0, s_side>>>();
    cudaEventRecord(ev_join, s_side);

    simexp_mma<<<NTRI, 256, SMEM_GEMM>>>();

    // join: final needs Epart (main) + Pc/Cf (side)
    cudaStreamWaitEvent(0, ev_join, 0);
    final_kernel<<<NROWS / 32, 256>>>(out);
}